// round 2
// baseline (speedup 1.0000x reference)
#include <cuda_runtime.h>

#define NQ   2048
#define NS   320
#define DIM  256
#define NWAY 20

typedef unsigned long long u64;

__device__ float g_qproj[NQ * DIM];   // query @ W1[:256]              (raw)
__device__ float g_sproj[NS * DIM];   // support @ W1[256:] + b1       (raw)
__device__ float g_Ts[NS];            // sum_d g_sproj[s,d] * W2[d]

// ---- packed f32x2 helpers ----
__device__ __forceinline__ u64 add2(u64 a, u64 b) {
    u64 d; asm("add.rn.f32x2 %0, %1, %2;" : "=l"(d) : "l"(a), "l"(b)); return d;
}
__device__ __forceinline__ u64 fma2(u64 a, u64 b, u64 c) {
    u64 d; asm("fma.rn.f32x2 %0, %1, %2, %3;" : "=l"(d) : "l"(a), "l"(b), "l"(c)); return d;
}
__device__ __forceinline__ u64 dup2(float x) {
    u64 r; unsigned xi = __float_as_uint(x);
    asm("mov.b64 %0, {%1, %1};" : "=l"(r) : "r"(xi)); return r;
}
__device__ __forceinline__ float lo2(u64 v) { return __uint_as_float((unsigned)v); }
__device__ __forceinline__ float hi2(u64 v) { return __uint_as_float((unsigned)(v >> 32)); }

// ---------------------------------------------------------------------------
// Kernel A: projections, FFMA2 outer product
// ---------------------------------------------------------------------------
#define BM 64
#define BN 64
#define BK 16
#define LDA 68

__global__ void __launch_bounds__(256) proj_kernel(
    const float* __restrict__ support, const float* __restrict__ query,
    const float* __restrict__ W1, const float* __restrict__ b1)
{
    __shared__ __align__(16) float As[BK][LDA];
    __shared__ __align__(16) float Bs[BK][LDA];

    const int tile_n = blockIdx.x;
    const int tile_m = blockIdx.y;
    const bool is_sup = (tile_m >= NQ / BM);

    const float* Amat;
    const float* Bmat;
    int m0;
    if (is_sup) { m0 = (tile_m - NQ / BM) * BM; Amat = support; Bmat = W1 + DIM * DIM; }
    else        { m0 = tile_m * BM;             Amat = query;   Bmat = W1; }
    const int n0 = tile_n * BN;

    const int tid = threadIdx.x;
    const int tx = tid & 15;
    const int ty = tid >> 4;

    const int arow = tid >> 2;
    const int ak4  = tid & 3;
    const int brow = tid >> 4;
    const int bc4  = tid & 15;

    u64 acc[4][2];
    #pragma unroll
    for (int i = 0; i < 4; i++) { acc[i][0] = 0ull; acc[i][1] = 0ull; }

    for (int k0 = 0; k0 < DIM; k0 += BK) {
        float4 av = *(const float4*)(Amat + (m0 + arow) * DIM + k0 + ak4 * 4);
        As[ak4 * 4 + 0][arow] = av.x;
        As[ak4 * 4 + 1][arow] = av.y;
        As[ak4 * 4 + 2][arow] = av.z;
        As[ak4 * 4 + 3][arow] = av.w;
        *(float4*)&Bs[brow][bc4 * 4] =
            *(const float4*)(Bmat + (k0 + brow) * DIM + n0 + bc4 * 4);
        __syncthreads();

        #pragma unroll
        for (int k = 0; k < BK; k++) {
            float4 a = *(const float4*)&As[k][ty * 4];
            ulonglong2 b = *(const ulonglong2*)&Bs[k][tx * 4];
            u64 a0 = dup2(a.x), a1 = dup2(a.y), a2 = dup2(a.z), a3 = dup2(a.w);
            acc[0][0] = fma2(a0, b.x, acc[0][0]); acc[0][1] = fma2(a0, b.y, acc[0][1]);
            acc[1][0] = fma2(a1, b.x, acc[1][0]); acc[1][1] = fma2(a1, b.y, acc[1][1]);
            acc[2][0] = fma2(a2, b.x, acc[2][0]); acc[2][1] = fma2(a2, b.y, acc[2][1]);
            acc[3][0] = fma2(a3, b.x, acc[3][0]); acc[3][1] = fma2(a3, b.y, acc[3][1]);
        }
        __syncthreads();
    }

    #pragma unroll
    for (int i = 0; i < 4; i++) {
        const int m = m0 + ty * 4 + i;
        float v[4] = { lo2(acc[i][0]), hi2(acc[i][0]), lo2(acc[i][1]), hi2(acc[i][1]) };
        #pragma unroll
        for (int j = 0; j < 4; j++) {
            const int n = n0 + tx * 4 + j;
            if (is_sup) g_sproj[m * DIM + n] = v[j] + __ldg(b1 + n);
            else        g_qproj[m * DIM + n] = v[j];
        }
    }
}

// ---------------------------------------------------------------------------
// Kernel A2: Ts[s] = sum_d g_sproj[s,d] * W2[d]   (tiny)
// ---------------------------------------------------------------------------
__global__ void __launch_bounds__(256) rowsum_kernel(const float* __restrict__ W2)
{
    const int warp = threadIdx.x >> 5, lane = threadIdx.x & 31;
    const int r0 = blockIdx.x * 32 + warp * 4;
    const float4* w4 = (const float4*)W2;
    float4 w1 = w4[lane * 2], w2v = w4[lane * 2 + 1];
    #pragma unroll
    for (int r = 0; r < 4; r++) {
        const int row = r0 + r;
        const float4* sp4 = (const float4*)(g_sproj + row * DIM);
        float4 s1 = sp4[lane * 2], s2 = sp4[lane * 2 + 1];
        float t = s1.x * w1.x + s1.y * w1.y + s1.z * w1.z + s1.w * w1.w
                + s2.x * w2v.x + s2.y * w2v.y + s2.z * w2v.z + s2.w * w2v.w;
        #pragma unroll
        for (int o = 16; o > 0; o >>= 1) t += __shfl_xor_sync(0xffffffffu, t, o);
        if (lane == 0) g_Ts[row] = t;
    }
}

// ---------------------------------------------------------------------------
// Kernel B: scores + softmax + one-hot aggregation.
//   score'[q,s] = 0.5*(Ts[s] + sum_d |qp+sp| * W2[d])   (per-q constant dropped)
// 8 warps: warp w -> q-group (w&3, 4 q's), s-half (w>>2, 160 s = 5 chunks of 32)
// ---------------------------------------------------------------------------
#define QB 16
#define SPAD 260
#define ABSMASK 0x7FFFFFFF7FFFFFFFull

__device__ __forceinline__ void cpa16(float* dst, const float* src) {
    unsigned sa = (unsigned)__cvta_generic_to_shared(dst);
    asm volatile("cp.async.cg.shared.global [%0], [%1], 16;" :: "r"(sa), "l"(src));
}

// team = tid>>7; chunk c covers s in [team*160 + c*32, +32)
__device__ __forceinline__ void prefetch_chunk(float* buf, int team, int c, int tteam) {
    const int s0 = team * 160 + c * 32;
    #pragma unroll
    for (int i = 0; i < 16; i++) {
        int f   = tteam + i * 128;   // 0..2047
        int row = f >> 6;            // 0..31
        int c4  = f & 63;            // 0..63
        cpa16(buf + row * SPAD + c4 * 4, g_sproj + (s0 + row) * DIM + c4 * 4);
    }
    asm volatile("cp.async.commit_group;");
}

__global__ void __launch_bounds__(256, 1) score_kernel(
    const int* __restrict__ labels, const float* __restrict__ W2,
    float* __restrict__ out)
{
    extern __shared__ float sm[];
    float* sp   = sm;                          // 4 * 8320 (team*2 + buf)
    float* qp   = sm + 4 * 8320;               // QB*256
    float* w2s  = qp + QB * DIM;               // 256
    float* ts   = w2s + DIM;                   // 320
    float* sacc = ts + NS;                     // QB*20
    float* wred = sacc + QB * NWAY;            // 32
    float* wsum = wred + 32;                   // 32
    int*   lbl  = (int*)(wsum + 32);           // 320

    const int tid   = threadIdx.x;
    const int warp  = tid >> 5;
    const int lane  = tid & 31;
    const int qg    = warp & 3;
    const int team  = warp >> 2;               // == tid>>7
    const int tteam = tid & 127;
    const int qbase = blockIdx.x * QB;

    prefetch_chunk(sp + (team * 2) * 8320, team, 0, tteam);

    // prologue loads
    {
        const float4* qsrc = (const float4*)(g_qproj + qbase * DIM);
        float4* qpv = (float4*)qp;
        #pragma unroll
        for (int i = 0; i < 4; i++) qpv[tid + i * 256] = qsrc[tid + i * 256];
        if (tid < DIM / 4) ((float4*)w2s)[tid] = ((const float4*)W2)[tid];
        for (int i = tid; i < NS; i += 256) { ts[i] = g_Ts[i]; lbl[i] = labels[i]; }
        for (int i = tid; i < QB * NWAY; i += 256) sacc[i] = 0.f;
    }

    const ulonglong2* qr0 = (const ulonglong2*)(qp + (qg * 4 + 0) * DIM);
    const ulonglong2* qr1 = (const ulonglong2*)(qp + (qg * 4 + 1) * DIM);
    const ulonglong2* qr2 = (const ulonglong2*)(qp + (qg * 4 + 2) * DIM);
    const ulonglong2* qr3 = (const ulonglong2*)(qp + (qg * 4 + 3) * DIM);
    const ulonglong2* w2p = (const ulonglong2*)w2s;

    float sc[4][5];

    for (int c = 0; c < 5; c++) {
        asm volatile("cp.async.wait_group 0;");
        __syncthreads();
        float* cur = sp + (team * 2 + (c & 1)) * 8320;
        if (c + 1 < 5)
            prefetch_chunk(sp + (team * 2 + ((c + 1) & 1)) * 8320, team, c + 1, tteam);

        const ulonglong2* srow = (const ulonglong2*)(cur + lane * SPAD);
        u64 a00 = 0, a01 = 0, a10 = 0, a11 = 0, a20 = 0, a21 = 0, a30 = 0, a31 = 0;

        #pragma unroll 4
        for (int j = 0; j < 64; j++) {
            ulonglong2 sv = srow[j];
            ulonglong2 wv = w2p[j];
            u64 t;
            {
                ulonglong2 qv = qr0[j];
                t = add2(qv.x, sv.x) & ABSMASK; a00 = fma2(t, wv.x, a00);
                t = add2(qv.y, sv.y) & ABSMASK; a01 = fma2(t, wv.y, a01);
            }
            {
                ulonglong2 qv = qr1[j];
                t = add2(qv.x, sv.x) & ABSMASK; a10 = fma2(t, wv.x, a10);
                t = add2(qv.y, sv.y) & ABSMASK; a11 = fma2(t, wv.y, a11);
            }
            {
                ulonglong2 qv = qr2[j];
                t = add2(qv.x, sv.x) & ABSMASK; a20 = fma2(t, wv.x, a20);
                t = add2(qv.y, sv.y) & ABSMASK; a21 = fma2(t, wv.y, a21);
            }
            {
                ulonglong2 qv = qr3[j];
                t = add2(qv.x, sv.x) & ABSMASK; a30 = fma2(t, wv.x, a30);
                t = add2(qv.y, sv.y) & ABSMASK; a31 = fma2(t, wv.y, a31);
            }
        }
        const float tsv = ts[team * 160 + c * 32 + lane];
        sc[0][c] = 0.5f * (tsv + ((lo2(a00) + hi2(a00)) + (lo2(a01) + hi2(a01))));
        sc[1][c] = 0.5f * (tsv + ((lo2(a10) + hi2(a10)) + (lo2(a11) + hi2(a11))));
        sc[2][c] = 0.5f * (tsv + ((lo2(a20) + hi2(a20)) + (lo2(a21) + hi2(a21))));
        sc[3][c] = 0.5f * (tsv + ((lo2(a30) + hi2(a30)) + (lo2(a31) + hi2(a31))));
    }

    // ---- softmax across the two s-teams + class aggregation ----
    #pragma unroll
    for (int q = 0; q < 4; q++) {
        float m = sc[q][0];
        #pragma unroll
        for (int c = 1; c < 5; c++) m = fmaxf(m, sc[q][c]);
        #pragma unroll
        for (int o = 16; o > 0; o >>= 1)
            m = fmaxf(m, __shfl_xor_sync(0xffffffffu, m, o));
        if (lane == 0) wred[warp * 4 + q] = m;
    }
    __syncthreads();

    float gm[4];
    #pragma unroll
    for (int q = 0; q < 4; q++)
        gm[q] = fmaxf(wred[warp * 4 + q], wred[(warp ^ 4) * 4 + q]);

    #pragma unroll
    for (int q = 0; q < 4; q++) {
        float l = 0.f;
        #pragma unroll
        for (int c = 0; c < 5; c++) {
            float ev = __expf(sc[q][c] - gm[q]);
            l += ev;
            atomicAdd(&sacc[(qg * 4 + q) * NWAY + lbl[team * 160 + c * 32 + lane]], ev);
        }
        #pragma unroll
        for (int o = 16; o > 0; o >>= 1)
            l += __shfl_xor_sync(0xffffffffu, l, o);
        if (lane == 0) wsum[warp * 4 + q] = l;
    }
    __syncthreads();

    if (team == 0) {
        #pragma unroll
        for (int q = 0; q < 4; q++) {
            float invv = 1.f / (wsum[warp * 4 + q] + wsum[(warp + 4) * 4 + q]);
            const int qq = qbase + qg * 4 + q;
            if (lane < NWAY)
                out[qq * NWAY + lane] = sacc[(qg * 4 + q) * NWAY + lane] * invv;
        }
    }
}

// ---------------------------------------------------------------------------
extern "C" void kernel_launch(void* const* d_in, const int* in_sizes, int n_in,
                              void* d_out, int out_size)
{
    (void)in_sizes; (void)n_in; (void)out_size;
    const float* support = (const float*)d_in[0];
    const float* query   = (const float*)d_in[1];
    const int*   labels  = (const int*)d_in[2];
    const float* W1      = (const float*)d_in[3];
    const float* b1      = (const float*)d_in[4];
    const float* W2      = (const float*)d_in[5];
    float* out = (float*)d_out;

    proj_kernel<<<dim3(4, 37), 256>>>(support, query, W1, b1);
    rowsum_kernel<<<10, 256>>>(W2);

    const int smem_bytes = (4 * 8320 + QB * DIM + DIM + NS + QB * NWAY + 64) * 4
                           + NS * 4;
    cudaFuncSetAttribute(score_kernel,
                         cudaFuncAttributeMaxDynamicSharedMemorySize, smem_bytes);
    score_kernel<<<NQ / QB, 256, smem_bytes>>>(labels, W2, out);
}

// round 3
// speedup vs baseline: 1.0835x; 1.0835x over previous
#include <cuda_runtime.h>

#define NQ   2048
#define NS   320
#define DIM  256
#define NWAY 20

typedef unsigned long long u64;

__device__ float g_qproj[NQ * DIM];
__device__ float g_sproj[NS * DIM];
__device__ float g_Ts[NS];

// ---- packed f32x2 helpers ----
__device__ __forceinline__ u64 add2(u64 a, u64 b) {
    u64 d; asm("add.rn.f32x2 %0, %1, %2;" : "=l"(d) : "l"(a), "l"(b)); return d;
}
__device__ __forceinline__ u64 fma2(u64 a, u64 b, u64 c) {
    u64 d; asm("fma.rn.f32x2 %0, %1, %2, %3;" : "=l"(d) : "l"(a), "l"(b), "l"(c)); return d;
}
__device__ __forceinline__ float lo2(u64 v) { return __uint_as_float((unsigned)v); }
__device__ __forceinline__ float hi2(u64 v) { return __uint_as_float((unsigned)(v >> 32)); }

// ---------------------------------------------------------------------------
// Kernel A: projections — round-1 proven scalar-FFMA version
// ---------------------------------------------------------------------------
#define BM 64
#define BN 64
#define BK 16
#define LDA 68

__global__ void __launch_bounds__(256) proj_kernel(
    const float* __restrict__ support, const float* __restrict__ query,
    const float* __restrict__ W1, const float* __restrict__ b1)
{
    __shared__ __align__(16) float As[BK][LDA];
    __shared__ __align__(16) float Bs[BK][LDA];

    const int tile_n = blockIdx.x;
    const int tile_m = blockIdx.y;
    const bool is_sup = (tile_m >= NQ / BM);

    const float* Amat;
    const float* Bmat;
    int m0;
    if (is_sup) { m0 = (tile_m - NQ / BM) * BM; Amat = support; Bmat = W1 + DIM * DIM; }
    else        { m0 = tile_m * BM;             Amat = query;   Bmat = W1; }
    const int n0 = tile_n * BN;

    const int tid = threadIdx.x;
    const int tx = tid & 15;
    const int ty = tid >> 4;

    const int arow = tid >> 2;
    const int ak4  = tid & 3;
    const int brow = tid >> 4;
    const int bc4  = tid & 15;

    float acc[4][4];
    #pragma unroll
    for (int i = 0; i < 4; i++)
        #pragma unroll
        for (int j = 0; j < 4; j++) acc[i][j] = 0.f;

    for (int k0 = 0; k0 < DIM; k0 += BK) {
        float4 av = *(const float4*)(Amat + (m0 + arow) * DIM + k0 + ak4 * 4);
        As[ak4 * 4 + 0][arow] = av.x;
        As[ak4 * 4 + 1][arow] = av.y;
        As[ak4 * 4 + 2][arow] = av.z;
        As[ak4 * 4 + 3][arow] = av.w;
        *(float4*)&Bs[brow][bc4 * 4] =
            *(const float4*)(Bmat + (k0 + brow) * DIM + n0 + bc4 * 4);
        __syncthreads();

        #pragma unroll
        for (int k = 0; k < BK; k++) {
            float4 a = *(const float4*)&As[k][ty * 4];
            float4 b = *(const float4*)&Bs[k][tx * 4];
            acc[0][0] = fmaf(a.x, b.x, acc[0][0]);
            acc[0][1] = fmaf(a.x, b.y, acc[0][1]);
            acc[0][2] = fmaf(a.x, b.z, acc[0][2]);
            acc[0][3] = fmaf(a.x, b.w, acc[0][3]);
            acc[1][0] = fmaf(a.y, b.x, acc[1][0]);
            acc[1][1] = fmaf(a.y, b.y, acc[1][1]);
            acc[1][2] = fmaf(a.y, b.z, acc[1][2]);
            acc[1][3] = fmaf(a.y, b.w, acc[1][3]);
            acc[2][0] = fmaf(a.z, b.x, acc[2][0]);
            acc[2][1] = fmaf(a.z, b.y, acc[2][1]);
            acc[2][2] = fmaf(a.z, b.z, acc[2][2]);
            acc[2][3] = fmaf(a.z, b.w, acc[2][3]);
            acc[3][0] = fmaf(a.w, b.x, acc[3][0]);
            acc[3][1] = fmaf(a.w, b.y, acc[3][1]);
            acc[3][2] = fmaf(a.w, b.z, acc[3][2]);
            acc[3][3] = fmaf(a.w, b.w, acc[3][3]);
        }
        __syncthreads();
    }

    #pragma unroll
    for (int i = 0; i < 4; i++) {
        const int m = m0 + ty * 4 + i;
        #pragma unroll
        for (int j = 0; j < 4; j++) {
            const int n = n0 + tx * 4 + j;
            float v = acc[i][j];
            if (is_sup) g_sproj[m * DIM + n] = v + __ldg(b1 + n);
            else        g_qproj[m * DIM + n] = v;
        }
    }
}

// ---------------------------------------------------------------------------
// Kernel A2: Ts[s] = sum_d g_sproj[s,d] * W2[d]
// ---------------------------------------------------------------------------
__global__ void __launch_bounds__(256) rowsum_kernel(const float* __restrict__ W2)
{
    const int warp = threadIdx.x >> 5, lane = threadIdx.x & 31;
    const int r0 = blockIdx.x * 32 + warp * 4;
    const float4* w4 = (const float4*)W2;
    float4 w1 = w4[lane * 2], w2v = w4[lane * 2 + 1];
    #pragma unroll
    for (int r = 0; r < 4; r++) {
        const int row = r0 + r;
        const float4* sp4 = (const float4*)(g_sproj + row * DIM);
        float4 s1 = sp4[lane * 2], s2 = sp4[lane * 2 + 1];
        float t = s1.x * w1.x + s1.y * w1.y + s1.z * w1.z + s1.w * w1.w
                + s2.x * w2v.x + s2.y * w2v.y + s2.z * w2v.z + s2.w * w2v.w;
        #pragma unroll
        for (int o = 16; o > 0; o >>= 1) t += __shfl_xor_sync(0xffffffffu, t, o);
        if (lane == 0) g_Ts[row] = t;
    }
}

// ---------------------------------------------------------------------------
// Kernel B: 512 threads = 4 qgroups x 4 d-teams. Shared s-chunk pipeline.
//   part[q][s] = sum_d |qp+sp| * W2[d]   (accumulated by 4 teams)
//   score = 0.5*(Ts[s] + part[q][s]); warp w does softmax for q=w.
// ---------------------------------------------------------------------------
#define QB 16
#define TPB 512
#define SPAD 260
#define CHUNKF 8320    // 32 * 260
#define ABSMASK 0x7FFFFFFF7FFFFFFFull

__device__ __forceinline__ void cpa16(float* dst, const float* src) {
    unsigned sa = (unsigned)__cvta_generic_to_shared(dst);
    asm volatile("cp.async.cg.shared.global [%0], [%1], 16;" :: "r"(sa), "l"(src));
}

__device__ __forceinline__ void prefetch_chunk(float* buf, int c, int tid) {
    #pragma unroll
    for (int i = 0; i < 4; i++) {
        int f   = tid + i * TPB;     // float4 index 0..2047
        int row = f >> 6;            // 0..31
        int c4  = f & 63;            // 0..63
        cpa16(buf + row * SPAD + c4 * 4, g_sproj + (c * 32 + row) * DIM + c4 * 4);
    }
    asm volatile("cp.async.commit_group;");
}

__global__ void __launch_bounds__(TPB, 1) score_kernel(
    const int* __restrict__ labels, const float* __restrict__ W2,
    float* __restrict__ out)
{
    extern __shared__ float sm[];
    float* sp   = sm;                          // 2 * 8320
    float* qp   = sm + 2 * CHUNKF;             // QB*256 = 4096
    float* w2s  = qp + QB * DIM;               // 256
    float* ts   = w2s + DIM;                   // 320
    float* part = ts + NS;                     // QB*NS = 5120
    float* sacc = part + QB * NS;              // QB*20 = 320
    int*   lbl  = (int*)(sacc + QB * NWAY);    // 320

    const int tid  = threadIdx.x;
    const int warp = tid >> 5;
    const int lane = tid & 31;
    const int qg   = warp & 3;                 // q-group: q in [qg*4, qg*4+4)
    const int team = warp >> 2;                // d-quarter: d in [team*64, +64)
    const int qbase = blockIdx.x * QB;

    prefetch_chunk(sp, 0, tid);

    // prologue
    {
        const float4* qsrc = (const float4*)(g_qproj + qbase * DIM);
        float4* qpv = (float4*)qp;
        #pragma unroll
        for (int i = 0; i < 2; i++) qpv[tid + i * TPB] = qsrc[tid + i * TPB];
        if (tid < DIM / 4) ((float4*)w2s)[tid] = ((const float4*)W2)[tid];
        if (tid < NS) { ts[tid] = g_Ts[tid]; lbl[tid] = labels[tid]; }
        #pragma unroll
        for (int i = 0; i < QB * NS / TPB; i++) part[tid + i * TPB] = 0.f;
        if (tid < QB * NWAY) sacc[tid] = 0.f;
    }

    const int doff = team * 64;                // float offset within a 256-d row
    const ulonglong2* qr0 = (const ulonglong2*)(qp + (qg * 4 + 0) * DIM + doff);
    const ulonglong2* qr1 = (const ulonglong2*)(qp + (qg * 4 + 1) * DIM + doff);
    const ulonglong2* qr2 = (const ulonglong2*)(qp + (qg * 4 + 2) * DIM + doff);
    const ulonglong2* qr3 = (const ulonglong2*)(qp + (qg * 4 + 3) * DIM + doff);
    const ulonglong2* w2p = (const ulonglong2*)(w2s + doff);

    for (int c = 0; c < 10; c++) {
        asm volatile("cp.async.wait_group 0;");
        __syncthreads();
        float* cur = sp + (c & 1) * CHUNKF;
        if (c + 1 < 10) prefetch_chunk(sp + ((c + 1) & 1) * CHUNKF, c + 1, tid);

        const ulonglong2* srow = (const ulonglong2*)(cur + lane * SPAD + doff);
        u64 a00 = 0, a01 = 0, a10 = 0, a11 = 0, a20 = 0, a21 = 0, a30 = 0, a31 = 0;

        #pragma unroll
        for (int j = 0; j < 16; j++) {
            ulonglong2 sv = srow[j];
            ulonglong2 wv = w2p[j];
            u64 t;
            {
                ulonglong2 qv = qr0[j];
                t = add2(qv.x, sv.x) & ABSMASK; a00 = fma2(t, wv.x, a00);
                t = add2(qv.y, sv.y) & ABSMASK; a01 = fma2(t, wv.y, a01);
            }
            {
                ulonglong2 qv = qr1[j];
                t = add2(qv.x, sv.x) & ABSMASK; a10 = fma2(t, wv.x, a10);
                t = add2(qv.y, sv.y) & ABSMASK; a11 = fma2(t, wv.y, a11);
            }
            {
                ulonglong2 qv = qr2[j];
                t = add2(qv.x, sv.x) & ABSMASK; a20 = fma2(t, wv.x, a20);
                t = add2(qv.y, sv.y) & ABSMASK; a21 = fma2(t, wv.y, a21);
            }
            {
                ulonglong2 qv = qr3[j];
                t = add2(qv.x, sv.x) & ABSMASK; a30 = fma2(t, wv.x, a30);
                t = add2(qv.y, sv.y) & ABSMASK; a31 = fma2(t, wv.y, a31);
            }
        }
        const int sidx = c * 32 + lane;
        atomicAdd(&part[(qg * 4 + 0) * NS + sidx],
                  (lo2(a00) + hi2(a00)) + (lo2(a01) + hi2(a01)));
        atomicAdd(&part[(qg * 4 + 1) * NS + sidx],
                  (lo2(a10) + hi2(a10)) + (lo2(a11) + hi2(a11)));
        atomicAdd(&part[(qg * 4 + 2) * NS + sidx],
                  (lo2(a20) + hi2(a20)) + (lo2(a21) + hi2(a21)));
        atomicAdd(&part[(qg * 4 + 3) * NS + sidx],
                  (lo2(a30) + hi2(a30)) + (lo2(a31) + hi2(a31)));
    }
    __syncthreads();

    // ---- softmax: warp w owns q = w ----
    {
        const int q = warp;
        float v[10];
        #pragma unroll
        for (int c = 0; c < 10; c++)
            v[c] = 0.5f * (ts[c * 32 + lane] + part[q * NS + c * 32 + lane]);

        float m = v[0];
        #pragma unroll
        for (int c = 1; c < 10; c++) m = fmaxf(m, v[c]);
        #pragma unroll
        for (int o = 16; o > 0; o >>= 1)
            m = fmaxf(m, __shfl_xor_sync(0xffffffffu, m, o));

        float l = 0.f;
        #pragma unroll
        for (int c = 0; c < 10; c++) {
            float ev = __expf(v[c] - m);
            l += ev;
            atomicAdd(&sacc[q * NWAY + lbl[c * 32 + lane]], ev);
        }
        #pragma unroll
        for (int o = 16; o > 0; o >>= 1)
            l += __shfl_xor_sync(0xffffffffu, l, o);
        const float inv = 1.f / l;
        __syncwarp();

        if (lane < NWAY)
            out[(qbase + q) * NWAY + lane] = sacc[q * NWAY + lane] * inv;
    }
}

// ---------------------------------------------------------------------------
extern "C" void kernel_launch(void* const* d_in, const int* in_sizes, int n_in,
                              void* d_out, int out_size)
{
    (void)in_sizes; (void)n_in; (void)out_size;
    const float* support = (const float*)d_in[0];
    const float* query   = (const float*)d_in[1];
    const int*   labels  = (const int*)d_in[2];
    const float* W1      = (const float*)d_in[3];
    const float* b1      = (const float*)d_in[4];
    const float* W2      = (const float*)d_in[5];
    float* out = (float*)d_out;

    proj_kernel<<<dim3(4, 37), 256>>>(support, query, W1, b1);
    rowsum_kernel<<<10, 256>>>(W2);

    const int smem_bytes =
        (2 * CHUNKF + QB * DIM + DIM + NS + QB * NS + QB * NWAY) * 4 + NS * 4;
    cudaFuncSetAttribute(score_kernel,
                         cudaFuncAttributeMaxDynamicSharedMemorySize, smem_bytes);
    score_kernel<<<NQ / QB, TPB, smem_bytes>>>(labels, W2, out);
}

// round 6
// speedup vs baseline: 1.1282x; 1.0412x over previous
#include <cuda_runtime.h>

#define NQ   2048
#define NS   320
#define DIM  256
#define NWAY 20

typedef unsigned long long u64;

__device__ float g_qproj[NQ * DIM];
__device__ float g_sproj[NS * DIM];
__device__ float g_Ts[NS];

// ---- packed f32x2 helpers ----
__device__ __forceinline__ u64 add2(u64 a, u64 b) {
    u64 d; asm("add.rn.f32x2 %0, %1, %2;" : "=l"(d) : "l"(a), "l"(b)); return d;
}
__device__ __forceinline__ u64 fma2(u64 a, u64 b, u64 c) {
    u64 d; asm("fma.rn.f32x2 %0, %1, %2, %3;" : "=l"(d) : "l"(a), "l"(b), "l"(c)); return d;
}
__device__ __forceinline__ u64 dup2(float x) {
    u64 r; unsigned xi = __float_as_uint(x);
    asm("mov.b64 %0, {%1, %1};" : "=l"(r) : "r"(xi)); return r;
}
__device__ __forceinline__ float lo2(u64 v) { return __uint_as_float((unsigned)v); }
__device__ __forceinline__ float hi2(u64 v) { return __uint_as_float((unsigned)(v >> 32)); }

__device__ __forceinline__ void cpa16(void* dst, const void* src) {
    unsigned sa = (unsigned)__cvta_generic_to_shared(dst);
    asm volatile("cp.async.cg.shared.global [%0], [%1], 16;" :: "r"(sa), "l"(src));
}

// ---------------------------------------------------------------------------
// Kernel A: projections. BM=BN=64, BK=64, double-buffered.
//   A: LDG->regs->STS as duplicated u64 (AsD[k][m] = {a,a})
//   B: cp.async (4 float4 per thread per stage), k-major Bs[k][n]
//   Compute per k: 4x LDS.64 (A dup, broadcast) + 1x LDS.128 (B pair) + 8 FFMA2
// ---------------------------------------------------------------------------
#define PBK   64
#define PADA  65            // u64 stride per k-row of AsD
#define PADB  68            // float stride per k-row of Bs
#define ASTG  (PBK * PADA)  // 4160 u64
#define BSTG  (PBK * PADB)  // 4352 float

__global__ void __launch_bounds__(256) proj_kernel(
    const float* __restrict__ support, const float* __restrict__ query,
    const float* __restrict__ W1, const float* __restrict__ b1)
{
    extern __shared__ __align__(16) unsigned char psm[];
    u64*   AsD = (u64*)psm;                  // 2 * ASTG
    float* Bs  = (float*)(AsD + 2 * ASTG);   // 2 * BSTG

    const int tile_n = blockIdx.x;
    const int tile_m = blockIdx.y;
    const bool is_sup = (tile_m >= NQ / 64);

    const float* Amat;
    const float* Bmat;
    int m0;
    if (is_sup) { m0 = (tile_m - NQ / 64) * 64; Amat = support; Bmat = W1 + DIM * DIM; }
    else        { m0 = tile_m * 64;             Amat = query;   Bmat = W1; }
    const int n0 = tile_n * 64;

    const int tid = threadIdx.x;
    const int tx = tid & 15;          // n: 4 floats = 2 u64
    const int ty = tid >> 4;          // m: 4 rows

    // A loader: row t_m, k chunks t_k + u*16 (u=0..3), each float4 = 4 k's
    const int t_m = tid >> 2;         // 0..63
    const int t_k = (tid & 3) * 4;    // 0,4,8,12

    // B loader: row (k) = tid>>2; per-row float4 chunks (tid&3)+u*4, u=0..3
    const int b_row = tid >> 2;       // 0..63
    const int b_q   = tid & 3;        // 0..3

    const float* Arow = Amat + (m0 + t_m) * DIM;
    const float* Brow = Bmat + b_row * DIM + n0;

    u64 acc[4][2];
    #pragma unroll
    for (int i = 0; i < 4; i++) { acc[i][0] = 0ull; acc[i][1] = 0ull; }

    float4 areg[4];

    // ---- prologue: stage 0 ----
    #pragma unroll
    for (int u = 0; u < 4; u++)
        areg[u] = *(const float4*)(Arow + t_k + u * 16);
    #pragma unroll
    for (int u = 0; u < 4; u++) {
        const int kk = t_k + u * 16;
        AsD[(kk + 0) * PADA + t_m] = dup2(areg[u].x);
        AsD[(kk + 1) * PADA + t_m] = dup2(areg[u].y);
        AsD[(kk + 2) * PADA + t_m] = dup2(areg[u].z);
        AsD[(kk + 3) * PADA + t_m] = dup2(areg[u].w);
    }
    #pragma unroll
    for (int u = 0; u < 4; u++) {
        const int c4 = b_q + u * 4;   // 0..15
        cpa16(&Bs[b_row * PADB + c4 * 4], Brow + c4 * 4);
    }
    asm volatile("cp.async.commit_group;");

    #pragma unroll
    for (int s = 0; s < 4; s++) {
        const int buf = s & 1;
        asm volatile("cp.async.wait_group 0;");
        __syncthreads();

        if (s < 3) {
            const int k0n = (s + 1) * PBK;
            #pragma unroll
            for (int u = 0; u < 4; u++)
                areg[u] = *(const float4*)(Arow + k0n + t_k + u * 16);
            #pragma unroll
            for (int u = 0; u < 4; u++) {
                const int c4 = b_q + u * 4;
                cpa16(&Bs[(buf ^ 1) * BSTG + b_row * PADB + c4 * 4],
                      Brow + k0n * DIM + c4 * 4);
            }
            asm volatile("cp.async.commit_group;");
        }

        const u64*   aB = AsD + buf * ASTG + ty * 4;
        const float* bB = Bs + buf * BSTG + tx * 4;

        #pragma unroll 8
        for (int k = 0; k < PBK; k++) {
            ulonglong2 b = *(const ulonglong2*)(bB + k * PADB);
            u64 a0 = aB[k * PADA + 0];
            u64 a1 = aB[k * PADA + 1];
            u64 a2 = aB[k * PADA + 2];
            u64 a3 = aB[k * PADA + 3];
            acc[0][0] = fma2(a0, b.x, acc[0][0]); acc[0][1] = fma2(a0, b.y, acc[0][1]);
            acc[1][0] = fma2(a1, b.x, acc[1][0]); acc[1][1] = fma2(a1, b.y, acc[1][1]);
            acc[2][0] = fma2(a2, b.x, acc[2][0]); acc[2][1] = fma2(a2, b.y, acc[2][1]);
            acc[3][0] = fma2(a3, b.x, acc[3][0]); acc[3][1] = fma2(a3, b.y, acc[3][1]);
        }

        if (s < 3) {
            u64* dst = AsD + (buf ^ 1) * ASTG;
            #pragma unroll
            for (int u = 0; u < 4; u++) {
                const int kk = t_k + u * 16;
                dst[(kk + 0) * PADA + t_m] = dup2(areg[u].x);
                dst[(kk + 1) * PADA + t_m] = dup2(areg[u].y);
                dst[(kk + 2) * PADA + t_m] = dup2(areg[u].z);
                dst[(kk + 3) * PADA + t_m] = dup2(areg[u].w);
            }
        }
    }

    #pragma unroll
    for (int i = 0; i < 4; i++) {
        const int m = m0 + ty * 4 + i;
        float v[4] = { lo2(acc[i][0]), hi2(acc[i][0]), lo2(acc[i][1]), hi2(acc[i][1]) };
        #pragma unroll
        for (int j = 0; j < 4; j++) {
            const int n = n0 + tx * 4 + j;
            if (is_sup) g_sproj[m * DIM + n] = v[j] + __ldg(b1 + n);
            else        g_qproj[m * DIM + n] = v[j];
        }
    }
}

// ---------------------------------------------------------------------------
// Kernel A2: Ts[s] = sum_d g_sproj[s,d] * W2[d]
// ---------------------------------------------------------------------------
__global__ void __launch_bounds__(256) rowsum_kernel(const float* __restrict__ W2)
{
    const int warp = threadIdx.x >> 5, lane = threadIdx.x & 31;
    const int r0 = blockIdx.x * 32 + warp * 4;
    const float4* w4 = (const float4*)W2;
    float4 w1 = w4[lane * 2], w2v = w4[lane * 2 + 1];
    #pragma unroll
    for (int r = 0; r < 4; r++) {
        const int row = r0 + r;
        const float4* sp4 = (const float4*)(g_sproj + row * DIM);
        float4 s1 = sp4[lane * 2], s2 = sp4[lane * 2 + 1];
        float t = s1.x * w1.x + s1.y * w1.y + s1.z * w1.z + s1.w * w1.w
                + s2.x * w2v.x + s2.y * w2v.y + s2.z * w2v.z + s2.w * w2v.w;
        #pragma unroll
        for (int o = 16; o > 0; o >>= 1) t += __shfl_xor_sync(0xffffffffu, t, o);
        if (lane == 0) g_Ts[row] = t;
    }
}

// ---------------------------------------------------------------------------
// Kernel B: unchanged (512 thr = 4 qgroups x 4 d-teams)
// ---------------------------------------------------------------------------
#define QB 16
#define TPB 512
#define SPAD 260
#define CHUNKF 8320
#define ABSMASK 0x7FFFFFFF7FFFFFFFull

__device__ __forceinline__ void prefetch_chunk(float* buf, int c, int tid) {
    #pragma unroll
    for (int i = 0; i < 4; i++) {
        int f   = tid + i * TPB;
        int row = f >> 6;
        int c4  = f & 63;
        cpa16(buf + row * SPAD + c4 * 4, g_sproj + (c * 32 + row) * DIM + c4 * 4);
    }
    asm volatile("cp.async.commit_group;");
}

__global__ void __launch_bounds__(TPB, 1) score_kernel(
    const int* __restrict__ labels, const float* __restrict__ W2,
    float* __restrict__ out)
{
    extern __shared__ float sm[];
    float* sp   = sm;
    float* qp   = sm + 2 * CHUNKF;
    float* w2s  = qp + QB * DIM;
    float* ts   = w2s + DIM;
    float* part = ts + NS;
    float* sacc = part + QB * NS;
    int*   lbl  = (int*)(sacc + QB * NWAY);

    const int tid  = threadIdx.x;
    const int warp = tid >> 5;
    const int lane = tid & 31;
    const int qg   = warp & 3;
    const int team = warp >> 2;
    const int qbase = blockIdx.x * QB;

    prefetch_chunk(sp, 0, tid);

    {
        const float4* qsrc = (const float4*)(g_qproj + qbase * DIM);
        float4* qpv = (float4*)qp;
        #pragma unroll
        for (int i = 0; i < 2; i++) qpv[tid + i * TPB] = qsrc[tid + i * TPB];
        if (tid < DIM / 4) ((float4*)w2s)[tid] = ((const float4*)W2)[tid];
        if (tid < NS) { ts[tid] = g_Ts[tid]; lbl[tid] = labels[tid]; }
        #pragma unroll
        for (int i = 0; i < QB * NS / TPB; i++) part[tid + i * TPB] = 0.f;
        if (tid < QB * NWAY) sacc[tid] = 0.f;
    }

    const int doff = team * 64;
    const ulonglong2* qr0 = (const ulonglong2*)(qp + (qg * 4 + 0) * DIM + doff);
    const ulonglong2* qr1 = (const ulonglong2*)(qp + (qg * 4 + 1) * DIM + doff);
    const ulonglong2* qr2 = (const ulonglong2*)(qp + (qg * 4 + 2) * DIM + doff);
    const ulonglong2* qr3 = (const ulonglong2*)(qp + (qg * 4 + 3) * DIM + doff);
    const ulonglong2* w2p = (const ulonglong2*)(w2s + doff);

    for (int c = 0; c < 10; c++) {
        asm volatile("cp.async.wait_group 0;");
        __syncthreads();
        float* cur = sp + (c & 1) * CHUNKF;
        if (c + 1 < 10) prefetch_chunk(sp + ((c + 1) & 1) * CHUNKF, c + 1, tid);

        const ulonglong2* srow = (const ulonglong2*)(cur + lane * SPAD + doff);
        u64 a00 = 0, a01 = 0, a10 = 0, a11 = 0, a20 = 0, a21 = 0, a30 = 0, a31 = 0;

        #pragma unroll
        for (int j = 0; j < 16; j++) {
            ulonglong2 sv = srow[j];
            ulonglong2 wv = w2p[j];
            u64 t;
            {
                ulonglong2 qv = qr0[j];
                t = add2(qv.x, sv.x) & ABSMASK; a00 = fma2(t, wv.x, a00);
                t = add2(qv.y, sv.y) & ABSMASK; a01 = fma2(t, wv.y, a01);
            }
            {
                ulonglong2 qv = qr1[j];
                t = add2(qv.x, sv.x) & ABSMASK; a10 = fma2(t, wv.x, a10);
                t = add2(qv.y, sv.y) & ABSMASK; a11 = fma2(t, wv.y, a11);
            }
            {
                ulonglong2 qv = qr2[j];
                t = add2(qv.x, sv.x) & ABSMASK; a20 = fma2(t, wv.x, a20);
                t = add2(qv.y, sv.y) & ABSMASK; a21 = fma2(t, wv.y, a21);
            }
            {
                ulonglong2 qv = qr3[j];
                t = add2(qv.x, sv.x) & ABSMASK; a30 = fma2(t, wv.x, a30);
                t = add2(qv.y, sv.y) & ABSMASK; a31 = fma2(t, wv.y, a31);
            }
        }
        const int sidx = c * 32 + lane;
        atomicAdd(&part[(qg * 4 + 0) * NS + sidx],
                  (lo2(a00) + hi2(a00)) + (lo2(a01) + hi2(a01)));
        atomicAdd(&part[(qg * 4 + 1) * NS + sidx],
                  (lo2(a10) + hi2(a10)) + (lo2(a11) + hi2(a11)));
        atomicAdd(&part[(qg * 4 + 2) * NS + sidx],
                  (lo2(a20) + hi2(a20)) + (lo2(a21) + hi2(a21)));
        atomicAdd(&part[(qg * 4 + 3) * NS + sidx],
                  (lo2(a30) + hi2(a30)) + (lo2(a31) + hi2(a31)));
    }
    __syncthreads();

    {
        const int q = warp;
        float v[10];
        #pragma unroll
        for (int c = 0; c < 10; c++)
            v[c] = 0.5f * (ts[c * 32 + lane] + part[q * NS + c * 32 + lane]);

        float m = v[0];
        #pragma unroll
        for (int c = 1; c < 10; c++) m = fmaxf(m, v[c]);
        #pragma unroll
        for (int o = 16; o > 0; o >>= 1)
            m = fmaxf(m, __shfl_xor_sync(0xffffffffu, m, o));

        float l = 0.f;
        #pragma unroll
        for (int c = 0; c < 10; c++) {
            float ev = __expf(v[c] - m);
            l += ev;
            atomicAdd(&sacc[q * NWAY + lbl[c * 32 + lane]], ev);
        }
        #pragma unroll
        for (int o = 16; o > 0; o >>= 1)
            l += __shfl_xor_sync(0xffffffffu, l, o);
        const float inv = 1.f / l;
        __syncwarp();

        if (lane < NWAY)
            out[(qbase + q) * NWAY + lane] = sacc[q * NWAY + lane] * inv;
    }
}

// ---------------------------------------------------------------------------
extern "C" void kernel_launch(void* const* d_in, const int* in_sizes, int n_in,
                              void* d_out, int out_size)
{
    (void)in_sizes; (void)n_in; (void)out_size;
    const float* support = (const float*)d_in[0];
    const float* query   = (const float*)d_in[1];
    const int*   labels  = (const int*)d_in[2];
    const float* W1      = (const float*)d_in[3];
    const float* b1      = (const float*)d_in[4];
    const float* W2      = (const float*)d_in[5];
    float* out = (float*)d_out;

    const int proj_smem = (2 * ASTG) * 8 + (2 * BSTG) * 4;  // 101376 B
    cudaFuncSetAttribute(proj_kernel,
                         cudaFuncAttributeMaxDynamicSharedMemorySize, proj_smem);
    proj_kernel<<<dim3(4, 37), 256, proj_smem>>>(support, query, W1, b1);

    rowsum_kernel<<<10, 256>>>(W2);

    const int smem_bytes =
        (2 * CHUNKF + QB * DIM + DIM + NS + QB * NS + QB * NWAY) * 4 + NS * 4;
    cudaFuncSetAttribute(score_kernel,
                         cudaFuncAttributeMaxDynamicSharedMemorySize, smem_bytes);
    score_kernel<<<NQ / QB, TPB, smem_bytes>>>(labels, W2, out);
}